// round 14
// baseline (speedup 1.0000x reference)
#include <cuda_runtime.h>
#include <cuda_bf16.h>
#include <math_constants.h>
#include <cstdint>

// Problem constants (fixed by the dataset)
#define B_  4
#define S_  1024
#define E_  1024
#define H_  16
#define D_  64
#define M_  (B_ * S_)

// Split-bf16 Q/K/V scratch. Q/K row-major [bh][s][d]; V transposed [bh][d][s].
__device__ __nv_bfloat16 g_qh[B_*H_*S_*D_], g_ql[B_*H_*S_*D_];
__device__ __nv_bfloat16 g_kh[B_*H_*S_*D_], g_kl[B_*H_*S_*D_];
__device__ __nv_bfloat16 g_vth[B_*H_*S_*D_], g_vtl[B_*H_*S_*D_];

// ---------------------------------------------------------------------------
// Helpers
// ---------------------------------------------------------------------------
__device__ __forceinline__ void mma16816(float* d, const uint32_t* a, const uint32_t* b) {
    asm volatile(
        "mma.sync.aligned.m16n8k16.row.col.f32.bf16.bf16.f32 "
        "{%0,%1,%2,%3}, {%4,%5,%6,%7}, {%8,%9}, {%0,%1,%2,%3};\n"
        : "+f"(d[0]), "+f"(d[1]), "+f"(d[2]), "+f"(d[3])
        : "r"(a[0]), "r"(a[1]), "r"(a[2]), "r"(a[3]), "r"(b[0]), "r"(b[1]));
}

__device__ __forceinline__ void mma1688_tf32(float* d, const uint32_t* a, const uint32_t* b) {
    asm volatile(
        "mma.sync.aligned.m16n8k8.row.col.f32.tf32.tf32.f32 "
        "{%0,%1,%2,%3}, {%4,%5,%6,%7}, {%8,%9}, {%0,%1,%2,%3};\n"
        : "+f"(d[0]), "+f"(d[1]), "+f"(d[2]), "+f"(d[3])
        : "r"(a[0]), "r"(a[1]), "r"(a[2]), "r"(a[3]), "r"(b[0]), "r"(b[1]));
}

__device__ __forceinline__ uint32_t to_tf32(float f) {
    uint32_t u;
    asm("cvt.rna.tf32.f32 %0, %1;" : "=r"(u) : "f"(f));
    return u;
}

__device__ __forceinline__ uint32_t pack_bf2(__nv_bfloat16 lo, __nv_bfloat16 hi) {
    uint32_t l = *(const unsigned short*)&lo;
    uint32_t h = *(const unsigned short*)&hi;
    return l | (h << 16);
}

__device__ __forceinline__ void split_bf16(float x, __nv_bfloat16& h, __nv_bfloat16& l) {
    h = __float2bfloat16(x);
    l = __float2bfloat16(x - __bfloat162float(h));
}

__device__ __forceinline__ uint32_t smem_u32(const void* p) {
    return (uint32_t)__cvta_generic_to_shared(p);
}

__device__ __forceinline__ void cp_async16(uint32_t dst, const void* src) {
    asm volatile("cp.async.cg.shared.global [%0], [%1], 16;\n" :: "r"(dst), "l"(src));
}

__device__ __forceinline__ void cp_commit() {
    asm volatile("cp.async.commit_group;" ::: "memory");
}

__device__ __forceinline__ void cp_wait1() {
    asm volatile("cp.async.wait_group 1;" ::: "memory");
}

__device__ __forceinline__ void cp_wait0() {
    asm volatile("cp.async.wait_group 0;" ::: "memory");
}

// ---------------------------------------------------------------------------
// QKV projection GEMM: TF32 single-pass. fp32 inputs straight from harness.
// Block tile 128x128x32, 256 threads, warp tile 64x32. blockIdx.z = Q/K/V.
// ---------------------------------------------------------------------------
#define TBM 128
#define TBN 128
#define TBK 32
#define LDA_W 36
#define LDB_W 136
#define ATW (128 * LDA_W)
#define BTW (TBK * LDB_W)
#define QKV_SMEM (2 * (ATW + BTW) * 4)

__device__ __forceinline__ void qkv_issue(
    float* sm, int st,
    const float* __restrict__ X, const float* __restrict__ W,
    int m0, int n0, int k0, int tid)
{
    float* Abase = sm + st * (ATW + BTW);
    float* Bbase = Abase + ATW;
    #pragma unroll
    for (int u = 0; u < 4; u++) {
        const int idx = tid + u * 256;
        const int row = idx >> 3, seg = idx & 7;
        cp_async16(smem_u32(Abase + row * LDA_W + seg * 4),
                   X + (m0 + row) * E_ + k0 + seg * 4);
    }
    #pragma unroll
    for (int u = 0; u < 4; u++) {
        const int idx = tid + u * 256;
        const int kr = idx >> 5, nq = idx & 31;
        cp_async16(smem_u32(Bbase + kr * LDB_W + nq * 4),
                   W + (k0 + kr) * E_ + n0 + nq * 4);
    }
    cp_commit();
}

__global__ __launch_bounds__(256)
void qkv_mma(const float* __restrict__ X,
             const float* __restrict__ Wq, const float* __restrict__ bq,
             const float* __restrict__ Wk, const float* __restrict__ bk,
             const float* __restrict__ Wv, const float* __restrict__ bv)
{
    extern __shared__ float qsm[];

    const int which = blockIdx.z;
    const float* __restrict__ W    = (which == 0) ? Wq : (which == 1) ? Wk : Wv;
    const float* __restrict__ bias = (which == 0) ? bq : (which == 1) ? bk : bv;

    const int m0 = blockIdx.y * TBM;
    const int n0 = blockIdx.x * TBN;
    const int tid  = threadIdx.x;
    const int warp = tid >> 5;
    const int lane = tid & 31;
    const int wm = (warp >> 2) * 64;
    const int wn = (warp & 3) * 32;

    float acc[4][4][4];
    #pragma unroll
    for (int i = 0; i < 4; i++)
        #pragma unroll
        for (int j = 0; j < 4; j++)
            #pragma unroll
            for (int r = 0; r < 4; r++) acc[i][j][r] = 0.f;

    qkv_issue(qsm, 0, X, W, m0, n0, 0, tid);
    qkv_issue(qsm, 1, X, W, m0, n0, TBK, tid);

    for (int i = 0; i < 32; i++) {
        const int st = i & 1;
        if (i < 30) cp_wait1(); else cp_wait0();
        __syncthreads();

        const float* As = qsm + st * (ATW + BTW);
        const float* Bs = As + ATW;

        #pragma unroll
        for (int ks = 0; ks < TBK; ks += 8) {
            uint32_t a[4][4];
            const int arow = wm + (lane >> 2);
            const int acol = ks + (lane & 3);
            #pragma unroll
            for (int im = 0; im < 4; im++) {
                const int r = arow + im * 16;
                a[im][0] = to_tf32(As[ r      * LDA_W + acol    ]);
                a[im][1] = to_tf32(As[(r + 8) * LDA_W + acol    ]);
                a[im][2] = to_tf32(As[ r      * LDA_W + acol + 4]);
                a[im][3] = to_tf32(As[(r + 8) * LDA_W + acol + 4]);
            }
            uint32_t bfr[4][2];
            const int bk0 = ks + (lane & 3);
            const int bn  = wn + (lane >> 2);
            #pragma unroll
            for (int jn = 0; jn < 4; jn++) {
                const int n = bn + jn * 8;
                bfr[jn][0] = to_tf32(Bs[ bk0      * LDB_W + n]);
                bfr[jn][1] = to_tf32(Bs[(bk0 + 4) * LDB_W + n]);
            }
            #pragma unroll
            for (int im = 0; im < 4; im++)
                #pragma unroll
                for (int jn = 0; jn < 4; jn++)
                    mma1688_tf32(acc[im][jn], a[im], bfr[jn]);
        }
        __syncthreads();
        if (i + 2 < 32)
            qkv_issue(qsm, st, X, W, m0, n0, (i + 2) * TBK, tid);
    }

    // ---- epilogue: add bias, split to bf16 hi/lo, write scratch ----
    if (which < 2) {
        __nv_bfloat16* __restrict__ oh = (which == 0) ? g_qh : g_kh;
        __nv_bfloat16* __restrict__ ol = (which == 0) ? g_ql : g_kl;
        #pragma unroll
        for (int jn = 0; jn < 4; jn++) {
            const int ncol = n0 + wn + jn * 8 + ((lane & 3) << 1);
            const int hh = ncol >> 6;
            const int d  = ncol & 63;
            const float b0v = bias[ncol], b1v = bias[ncol + 1];
            #pragma unroll
            for (int im = 0; im < 4; im++) {
                const int row = m0 + wm + im * 16 + (lane >> 2);
                const int bb = row >> 10;
                const int s  = row & (S_ - 1);
                const int base = ((bb * H_ + hh) * S_ + s) * D_ + d;
                __nv_bfloat16 h0, l0, h1, l1;
                split_bf16(acc[im][jn][0] + b0v, h0, l0);
                split_bf16(acc[im][jn][1] + b1v, h1, l1);
                *(uint32_t*)&oh[base] = pack_bf2(h0, h1);
                *(uint32_t*)&ol[base] = pack_bf2(l0, l1);
                split_bf16(acc[im][jn][2] + b0v, h0, l0);
                split_bf16(acc[im][jn][3] + b1v, h1, l1);
                *(uint32_t*)&oh[base + 8 * D_] = pack_bf2(h0, h1);
                *(uint32_t*)&ol[base + 8 * D_] = pack_bf2(l0, l1);
            }
        }
    } else {
        // V: scatter-transpose to [bh][d][s]
        #pragma unroll
        for (int jn = 0; jn < 4; jn++) {
            const int ncol = n0 + wn + jn * 8 + ((lane & 3) << 1);
            const int hh = ncol >> 6;
            const int d  = ncol & 63;
            const float b0v = bias[ncol], b1v = bias[ncol + 1];
            #pragma unroll
            for (int im = 0; im < 4; im++) {
                const int row = m0 + wm + im * 16 + (lane >> 2);
                const int bb = row >> 10;
                const int s  = row & (S_ - 1);
                const int vb = ((bb * H_ + hh) * D_ + d) * S_ + s;
                __nv_bfloat16 h, l;
                split_bf16(acc[im][jn][0] + b0v, h, l);
                g_vth[vb] = h;            g_vtl[vb] = l;
                split_bf16(acc[im][jn][1] + b1v, h, l);
                g_vth[vb + S_] = h;       g_vtl[vb + S_] = l;
                split_bf16(acc[im][jn][2] + b0v, h, l);
                g_vth[vb + 8] = h;        g_vtl[vb + 8] = l;
                split_bf16(acc[im][jn][3] + b1v, h, l);
                g_vth[vb + S_ + 8] = h;   g_vtl[vb + S_ + 8] = l;
            }
        }
    }
}

// ---------------------------------------------------------------------------
// MMA flash attention (bf16 3-pass) with cp.async 2-stage K/V pipeline.
// 128 threads (4 warps), 64 q rows per block. Q fragments hoisted to regs.
// ---------------------------------------------------------------------------
#define ALD 72
#define ATILE (64 * ALD)
#define AT_SMEM_BYTES ((2 + 8) * ATILE * 2)

__device__ __forceinline__ void attn_issue(
    __nv_bfloat16* stage_base, int bh, size_t qoff, int t0, int tid)
{
    #pragma unroll
    for (int u = 0; u < 4; u++) {
        const int idx = tid + u * 128;
        const int r  = idx >> 3;
        const int sg = (idx & 7) * 8;
        const uint32_t doff = (uint32_t)(r * ALD + sg);
        cp_async16(smem_u32(stage_base + 0 * ATILE + doff),
                   g_kh + qoff + (t0 + r) * D_ + sg);
        cp_async16(smem_u32(stage_base + 1 * ATILE + doff),
                   g_kl + qoff + (t0 + r) * D_ + sg);
        cp_async16(smem_u32(stage_base + 2 * ATILE + doff),
                   g_vth + (size_t)(bh * D_ + r) * S_ + t0 + sg);
        cp_async16(smem_u32(stage_base + 3 * ATILE + doff),
                   g_vtl + (size_t)(bh * D_ + r) * S_ + t0 + sg);
    }
    cp_commit();
}

__global__ __launch_bounds__(128)
void attn_mma(const int* __restrict__ lens, float* __restrict__ out)
{
    extern __shared__ char smem_raw[];
    __nv_bfloat16* Qh = (__nv_bfloat16*)smem_raw;
    __nv_bfloat16* Ql = Qh + ATILE;
    __nv_bfloat16* St = Ql + ATILE;   // stage s at St + s*4*ATILE

    const int bh = blockIdx.y;
    const int b  = bh >> 4;
    const int h  = bh & (H_ - 1);
    const int len = lens[b];
    const int q0 = blockIdx.x * 64;
    const int tid = threadIdx.x;

    // ---- Shortcut: whole block invalid -> uniform mean of V ----
    if (q0 >= len) {
        float* red = (float*)smem_raw;
        const int d = tid & 63;
        const int half = tid >> 6;
        const uint4* ph = (const uint4*)(g_vth + (bh * D_ + d) * S_) + half * 64;
        const uint4* pl = (const uint4*)(g_vtl + (bh * D_ + d) * S_) + half * 64;
        float a = 0.f;
        for (int i = 0; i < 64; i++) {
            uint4 xh = ph[i], xl = pl[i];
            const __nv_bfloat162* eh = (const __nv_bfloat162*)&xh;
            const __nv_bfloat162* el = (const __nv_bfloat162*)&xl;
            #pragma unroll
            for (int e = 0; e < 4; e++) {
                float2 fh = __bfloat1622float2(eh[e]);
                float2 fl = __bfloat1622float2(el[e]);
                a += fh.x + fh.y + fl.x + fl.y;
            }
        }
        red[half * 64 + d] = a;
        __syncthreads();
        const float m = (red[d] + red[64 + d]) * (1.0f / 1024.0f);
        for (int r = half; r < 64; r += 2)
            out[(b * S_ + q0 + r) * E_ + h * D_ + d] = m;
        return;
    }

    const int warp = tid >> 5;
    const int lane = tid & 31;
    const int wm = warp * 16;

    const size_t qoff = (size_t)bh * S_ * D_;

    const bool all_valid = (q0 + 64 <= len);
    const int kend = all_valid ? ((len + 63) & ~63) : S_;
    const int nt = kend >> 6;

    // Start pipeline
    attn_issue(St, bh, qoff, 0, tid);
    if (nt > 1) attn_issue(St + 4 * ATILE, bh, qoff, 64, tid);

    // Load Q (overlaps with in-flight cp.async)
    #pragma unroll
    for (int u = 0; u < 4; u++) {
        const int idx = tid + u * 128;
        const int r = idx >> 3, seg = idx & 7;
        *(uint4*)&Qh[r * ALD + seg * 8] = *(const uint4*)&g_qh[qoff + (q0 + r) * D_ + seg * 8];
        *(uint4*)&Ql[r * ALD + seg * 8] = *(const uint4*)&g_ql[qoff + (q0 + r) * D_ + seg * 8];
    }
    __syncthreads();

    // ---- Hoist Q fragments into registers (invariant across K tiles) ----
    uint32_t qah[4][4], qal[4][4];
    {
        const int ar = wm + (lane >> 2);
        #pragma unroll
        for (int kq = 0; kq < 4; kq++) {
            const int ac = kq * 16 + ((lane & 3) << 1);
            qah[kq][0] = *(const uint32_t*)&Qh[ ar      * ALD + ac    ];
            qah[kq][1] = *(const uint32_t*)&Qh[(ar + 8) * ALD + ac    ];
            qah[kq][2] = *(const uint32_t*)&Qh[ ar      * ALD + ac + 8];
            qah[kq][3] = *(const uint32_t*)&Qh[(ar + 8) * ALD + ac + 8];
            qal[kq][0] = *(const uint32_t*)&Ql[ ar      * ALD + ac    ];
            qal[kq][1] = *(const uint32_t*)&Ql[(ar + 8) * ALD + ac    ];
            qal[kq][2] = *(const uint32_t*)&Ql[ ar      * ALD + ac + 8];
            qal[kq][3] = *(const uint32_t*)&Ql[(ar + 8) * ALD + ac + 8];
        }
    }

    float m0 = -CUDART_INF_F, m1 = -CUDART_INF_F, l0 = 0.f, l1 = 0.f;
    float o[8][4];
    #pragma unroll
    for (int j = 0; j < 8; j++)
        #pragma unroll
        for (int e = 0; e < 4; e++) o[j][e] = 0.f;

    const float scale = 0.125f;
    const int r0g = q0 + wm + (lane >> 2);
    const int r1g = r0g + 8;
    const bool rv0 = r0g < len, rv1 = r1g < len;

    for (int ti = 0; ti < nt; ti++) {
        const int st = ti & 1;
        const int t0 = ti * 64;
        if (ti + 1 < nt) cp_wait1(); else cp_wait0();
        __syncthreads();

        const __nv_bfloat16* Kh  = St + st * 4 * ATILE;
        const __nv_bfloat16* Kl  = Kh + ATILE;
        const __nv_bfloat16* Vth = Kh + 2 * ATILE;
        const __nv_bfloat16* Vtl = Kh + 3 * ATILE;

        // ---- S = Q K^T (Q frags from registers) ----
        float sc[8][4];
        #pragma unroll
        for (int j = 0; j < 8; j++)
            #pragma unroll
            for (int e = 0; e < 4; e++) sc[j][e] = 0.f;

        #pragma unroll
        for (int kq = 0; kq < 4; kq++) {
            const int kk = kq * 16;
            #pragma unroll
            for (int j = 0; j < 8; j++) {
                const int br = j * 8 + (lane >> 2);
                const int bc = kk + ((lane & 3) << 1);
                uint32_t bhf[2], blf[2];
                bhf[0] = *(const uint32_t*)&Kh[br * ALD + bc    ];
                bhf[1] = *(const uint32_t*)&Kh[br * ALD + bc + 8];
                blf[0] = *(const uint32_t*)&Kl[br * ALD + bc    ];
                blf[1] = *(const uint32_t*)&Kl[br * ALD + bc + 8];
                mma16816(sc[j], qah[kq], bhf);
                mma16816(sc[j], qah[kq], blf);
                mma16816(sc[j], qal[kq], bhf);
            }
        }

        // ---- mask + scale ----
        #pragma unroll
        for (int j = 0; j < 8; j++) {
            const int c0 = t0 + j * 8 + ((lane & 3) << 1);
            const bool cv0 = c0 < len, cv1 = (c0 + 1) < len;
            sc[j][0] = (rv0 && cv0) ? sc[j][0] * scale : -1e9f;
            sc[j][1] = (rv0 && cv1) ? sc[j][1] * scale : -1e9f;
            sc[j][2] = (rv1 && cv0) ? sc[j][2] * scale : -1e9f;
            sc[j][3] = (rv1 && cv1) ? sc[j][3] * scale : -1e9f;
        }

        // ---- online softmax ----
        float vm0 = -CUDART_INF_F, vm1 = -CUDART_INF_F;
        #pragma unroll
        for (int j = 0; j < 8; j++) {
            vm0 = fmaxf(vm0, fmaxf(sc[j][0], sc[j][1]));
            vm1 = fmaxf(vm1, fmaxf(sc[j][2], sc[j][3]));
        }
        vm0 = fmaxf(vm0, __shfl_xor_sync(0xffffffffu, vm0, 1));
        vm0 = fmaxf(vm0, __shfl_xor_sync(0xffffffffu, vm0, 2));
        vm1 = fmaxf(vm1, __shfl_xor_sync(0xffffffffu, vm1, 1));
        vm1 = fmaxf(vm1, __shfl_xor_sync(0xffffffffu, vm1, 2));
        const float mn0 = fmaxf(m0, vm0);
        const float mn1 = fmaxf(m1, vm1);
        const float al0 = __expf(m0 - mn0);
        const float al1 = __expf(m1 - mn1);
        m0 = mn0; m1 = mn1;

        float s0 = 0.f, s1 = 0.f;
        #pragma unroll
        for (int j = 0; j < 8; j++) {
            sc[j][0] = __expf(sc[j][0] - mn0); s0 += sc[j][0];
            sc[j][1] = __expf(sc[j][1] - mn0); s0 += sc[j][1];
            sc[j][2] = __expf(sc[j][2] - mn1); s1 += sc[j][2];
            sc[j][3] = __expf(sc[j][3] - mn1); s1 += sc[j][3];
        }
        s0 += __shfl_xor_sync(0xffffffffu, s0, 1);
        s0 += __shfl_xor_sync(0xffffffffu, s0, 2);
        s1 += __shfl_xor_sync(0xffffffffu, s1, 1);
        s1 += __shfl_xor_sync(0xffffffffu, s1, 2);
        l0 = l0 * al0 + s0;
        l1 = l1 * al1 + s1;
        #pragma unroll
        for (int j = 0; j < 8; j++) {
            o[j][0] *= al0; o[j][1] *= al0;
            o[j][2] *= al1; o[j][3] *= al1;
        }

        // ---- O += P V ----
        #pragma unroll
        for (int kp = 0; kp < 4; kp++) {
            const int j0 = kp * 2, j1 = kp * 2 + 1;
            uint32_t pah[4], pal[4];
            {
                __nv_bfloat16 hx, lx, hy, ly;
                split_bf16(sc[j0][0], hx, lx); split_bf16(sc[j0][1], hy, ly);
                pah[0] = pack_bf2(hx, hy); pal[0] = pack_bf2(lx, ly);
                split_bf16(sc[j0][2], hx, lx); split_bf16(sc[j0][3], hy, ly);
                pah[1] = pack_bf2(hx, hy); pal[1] = pack_bf2(lx, ly);
                split_bf16(sc[j1][0], hx, lx); split_bf16(sc[j1][1], hy, ly);
                pah[2] = pack_bf2(hx, hy); pal[2] = pack_bf2(lx, ly);
                split_bf16(sc[j1][2], hx, lx); split_bf16(sc[j1][3], hy, ly);
                pah[3] = pack_bf2(hx, hy); pal[3] = pack_bf2(lx, ly);
            }
            #pragma unroll
            for (int j = 0; j < 8; j++) {
                const int br = j * 8 + (lane >> 2);
                const int bc = kp * 16 + ((lane & 3) << 1);
                uint32_t bhf[2], blf[2];
                bhf[0] = *(const uint32_t*)&Vth[br * ALD + bc    ];
                bhf[1] = *(const uint32_t*)&Vth[br * ALD + bc + 8];
                blf[0] = *(const uint32_t*)&Vtl[br * ALD + bc    ];
                blf[1] = *(const uint32_t*)&Vtl[br * ALD + bc + 8];
                mma16816(o[j], pah, bhf);
                mma16816(o[j], pah, blf);
                mma16816(o[j], pal, bhf);
            }
        }

        __syncthreads();
        if (ti + 2 < nt)
            attn_issue(St + st * 4 * ATILE, bh, qoff, (ti + 2) * 64, tid);
    }

    const float inv0 = 1.f / l0;
    const float inv1 = 1.f / l1;
    #pragma unroll
    for (int j = 0; j < 8; j++) {
        const int d = j * 8 + ((lane & 3) << 1);
        float2 w0 = make_float2(o[j][0] * inv0, o[j][1] * inv0);
        float2 w1 = make_float2(o[j][2] * inv1, o[j][3] * inv1);
        *(float2*)&out[(b * S_ + r0g) * E_ + h * D_ + d] = w0;
        *(float2*)&out[(b * S_ + r1g) * E_ + h * D_ + d] = w1;
    }
}

// ---------------------------------------------------------------------------
extern "C" void kernel_launch(void* const* d_in, const int* in_sizes, int n_in,
                              void* d_out, int out_size)
{
    const float* x   = (const float*)d_in[0];
    const float* Wq  = (const float*)d_in[1];
    const float* bq  = (const float*)d_in[2];
    const float* Wk  = (const float*)d_in[3];
    const float* bk  = (const float*)d_in[4];
    const float* Wv  = (const float*)d_in[5];
    const float* bv  = (const float*)d_in[6];
    const int*  lens = (const int*)d_in[7];
    float* out = (float*)d_out;

    // Projections: TF32 single-pass, reads X and W directly
    cudaFuncSetAttribute(qkv_mma,
                         cudaFuncAttributeMaxDynamicSharedMemorySize, QKV_SMEM);
    dim3 ggrid(E_ / TBN, M_ / TBM, 3);
    qkv_mma<<<ggrid, 256, QKV_SMEM>>>(x, Wq, bq, Wk, bk, Wv, bv);

    // Attention (bf16 3-pass, Q frags hoisted)
    cudaFuncSetAttribute(attn_mma,
                         cudaFuncAttributeMaxDynamicSharedMemorySize, AT_SMEM_BYTES);
    dim3 agrid(S_ / 64, B_ * H_);
    attn_mma<<<agrid, 128, AT_SMEM_BYTES>>>(lens, out);
}

// round 15
// speedup vs baseline: 1.0399x; 1.0399x over previous
#include <cuda_runtime.h>
#include <cuda_bf16.h>
#include <math_constants.h>
#include <cstdint>

// Problem constants (fixed by the dataset)
#define B_  4
#define S_  1024
#define E_  1024
#define H_  16
#define D_  64
#define M_  (B_ * S_)

// Split-bf16 Q/K/V scratch. Q/K row-major [bh][s][d]; V transposed [bh][d][s].
__device__ __nv_bfloat16 g_qh[B_*H_*S_*D_], g_ql[B_*H_*S_*D_];
__device__ __nv_bfloat16 g_kh[B_*H_*S_*D_], g_kl[B_*H_*S_*D_];
__device__ __nv_bfloat16 g_vth[B_*H_*S_*D_], g_vtl[B_*H_*S_*D_];

// ---------------------------------------------------------------------------
// Helpers
// ---------------------------------------------------------------------------
__device__ __forceinline__ void mma16816(float* d, const uint32_t* a, const uint32_t* b) {
    asm volatile(
        "mma.sync.aligned.m16n8k16.row.col.f32.bf16.bf16.f32 "
        "{%0,%1,%2,%3}, {%4,%5,%6,%7}, {%8,%9}, {%0,%1,%2,%3};\n"
        : "+f"(d[0]), "+f"(d[1]), "+f"(d[2]), "+f"(d[3])
        : "r"(a[0]), "r"(a[1]), "r"(a[2]), "r"(a[3]), "r"(b[0]), "r"(b[1]));
}

__device__ __forceinline__ void mma1688_tf32(float* d, const uint32_t* a, const uint32_t* b) {
    asm volatile(
        "mma.sync.aligned.m16n8k8.row.col.f32.tf32.tf32.f32 "
        "{%0,%1,%2,%3}, {%4,%5,%6,%7}, {%8,%9}, {%0,%1,%2,%3};\n"
        : "+f"(d[0]), "+f"(d[1]), "+f"(d[2]), "+f"(d[3])
        : "r"(a[0]), "r"(a[1]), "r"(a[2]), "r"(a[3]), "r"(b[0]), "r"(b[1]));
}

__device__ __forceinline__ uint32_t to_tf32(float f) {
    uint32_t u;
    asm("cvt.rna.tf32.f32 %0, %1;" : "=r"(u) : "f"(f));
    return u;
}

__device__ __forceinline__ uint32_t pack_bf2(__nv_bfloat16 lo, __nv_bfloat16 hi) {
    uint32_t l = *(const unsigned short*)&lo;
    uint32_t h = *(const unsigned short*)&hi;
    return l | (h << 16);
}

__device__ __forceinline__ void split_bf16(float x, __nv_bfloat16& h, __nv_bfloat16& l) {
    h = __float2bfloat16(x);
    l = __float2bfloat16(x - __bfloat162float(h));
}

__device__ __forceinline__ uint32_t smem_u32(const void* p) {
    return (uint32_t)__cvta_generic_to_shared(p);
}

__device__ __forceinline__ void cp_async16(uint32_t dst, const void* src) {
    asm volatile("cp.async.cg.shared.global [%0], [%1], 16;\n" :: "r"(dst), "l"(src));
}

__device__ __forceinline__ void cp_commit() {
    asm volatile("cp.async.commit_group;" ::: "memory");
}

__device__ __forceinline__ void cp_wait1() {
    asm volatile("cp.async.wait_group 1;" ::: "memory");
}

__device__ __forceinline__ void cp_wait0() {
    asm volatile("cp.async.wait_group 0;" ::: "memory");
}

// ---------------------------------------------------------------------------
// QKV projection GEMM: TF32 single-pass, tile 128x64 (halved N for less wave
// quantization). 256 threads, 8 warps, warp tile 32x32. blockIdx.z = Q/K/V.
// ---------------------------------------------------------------------------
#define TBM 128
#define TBN 64
#define TBK 32
#define LDA_W 36                 // A row stride in words (32 + 4)
#define LDB_W 72                 // B row stride in words (64 + 8)
#define ATW (TBM * LDA_W)
#define BTW (TBK * LDB_W)
#define QKV_SMEM (2 * (ATW + BTW) * 4)

__device__ __forceinline__ void qkv_issue(
    float* sm, int st,
    const float* __restrict__ X, const float* __restrict__ W,
    int m0, int n0, int k0, int tid)
{
    float* Abase = sm + st * (ATW + BTW);
    float* Bbase = Abase + ATW;
    #pragma unroll
    for (int u = 0; u < 4; u++) {
        const int idx = tid + u * 256;
        const int row = idx >> 3, seg = idx & 7;               // A: 128 rows x 8 f4
        cp_async16(smem_u32(Abase + row * LDA_W + seg * 4),
                   X + (m0 + row) * E_ + k0 + seg * 4);
    }
    #pragma unroll
    for (int u = 0; u < 2; u++) {
        const int idx = tid + u * 256;
        const int kr = idx >> 4, nq = idx & 15;                // B: 32 k x 16 f4
        cp_async16(smem_u32(Bbase + kr * LDB_W + nq * 4),
                   W + (k0 + kr) * E_ + n0 + nq * 4);
    }
    cp_commit();
}

__global__ __launch_bounds__(256)
void qkv_mma(const float* __restrict__ X,
             const float* __restrict__ Wq, const float* __restrict__ bq,
             const float* __restrict__ Wk, const float* __restrict__ bk,
             const float* __restrict__ Wv, const float* __restrict__ bv)
{
    extern __shared__ float qsm[];

    const int which = blockIdx.z;
    const float* __restrict__ W    = (which == 0) ? Wq : (which == 1) ? Wk : Wv;
    const float* __restrict__ bias = (which == 0) ? bq : (which == 1) ? bk : bv;

    const int m0 = blockIdx.y * TBM;
    const int n0 = blockIdx.x * TBN;
    const int tid  = threadIdx.x;
    const int warp = tid >> 5;
    const int lane = tid & 31;
    const int wm = (warp >> 1) * 32;   // 0,32,64,96
    const int wn = (warp & 1) * 32;    // 0,32

    float acc[2][4][4];
    #pragma unroll
    for (int i = 0; i < 2; i++)
        #pragma unroll
        for (int j = 0; j < 4; j++)
            #pragma unroll
            for (int r = 0; r < 4; r++) acc[i][j][r] = 0.f;

    qkv_issue(qsm, 0, X, W, m0, n0, 0, tid);
    qkv_issue(qsm, 1, X, W, m0, n0, TBK, tid);

    for (int i = 0; i < 32; i++) {
        const int st = i & 1;
        if (i < 30) cp_wait1(); else cp_wait0();
        __syncthreads();

        const float* As = qsm + st * (ATW + BTW);
        const float* Bs = As + ATW;

        #pragma unroll
        for (int ks = 0; ks < TBK; ks += 8) {
            uint32_t a[2][4];
            const int arow = wm + (lane >> 2);
            const int acol = ks + (lane & 3);
            #pragma unroll
            for (int im = 0; im < 2; im++) {
                const int r = arow + im * 16;
                a[im][0] = to_tf32(As[ r      * LDA_W + acol    ]);
                a[im][1] = to_tf32(As[(r + 8) * LDA_W + acol    ]);
                a[im][2] = to_tf32(As[ r      * LDA_W + acol + 4]);
                a[im][3] = to_tf32(As[(r + 8) * LDA_W + acol + 4]);
            }
            uint32_t bfr[4][2];
            const int bk0 = ks + (lane & 3);
            const int bn  = wn + (lane >> 2);
            #pragma unroll
            for (int jn = 0; jn < 4; jn++) {
                const int n = bn + jn * 8;
                bfr[jn][0] = to_tf32(Bs[ bk0      * LDB_W + n]);
                bfr[jn][1] = to_tf32(Bs[(bk0 + 4) * LDB_W + n]);
            }
            #pragma unroll
            for (int im = 0; im < 2; im++)
                #pragma unroll
                for (int jn = 0; jn < 4; jn++)
                    mma1688_tf32(acc[im][jn], a[im], bfr[jn]);
        }
        __syncthreads();
        if (i + 2 < 32)
            qkv_issue(qsm, st, X, W, m0, n0, (i + 2) * TBK, tid);
    }

    // ---- epilogue: add bias, split to bf16 hi/lo, write scratch ----
    if (which < 2) {
        __nv_bfloat16* __restrict__ oh = (which == 0) ? g_qh : g_kh;
        __nv_bfloat16* __restrict__ ol = (which == 0) ? g_ql : g_kl;
        #pragma unroll
        for (int jn = 0; jn < 4; jn++) {
            const int ncol = n0 + wn + jn * 8 + ((lane & 3) << 1);
            const int hh = ncol >> 6;
            const int d  = ncol & 63;
            const float b0v = bias[ncol], b1v = bias[ncol + 1];
            #pragma unroll
            for (int im = 0; im < 2; im++) {
                const int row = m0 + wm + im * 16 + (lane >> 2);
                const int bb = row >> 10;
                const int s  = row & (S_ - 1);
                const int base = ((bb * H_ + hh) * S_ + s) * D_ + d;
                __nv_bfloat16 h0, l0, h1, l1;
                split_bf16(acc[im][jn][0] + b0v, h0, l0);
                split_bf16(acc[im][jn][1] + b1v, h1, l1);
                *(uint32_t*)&oh[base] = pack_bf2(h0, h1);
                *(uint32_t*)&ol[base] = pack_bf2(l0, l1);
                split_bf16(acc[im][jn][2] + b0v, h0, l0);
                split_bf16(acc[im][jn][3] + b1v, h1, l1);
                *(uint32_t*)&oh[base + 8 * D_] = pack_bf2(h0, h1);
                *(uint32_t*)&ol[base + 8 * D_] = pack_bf2(l0, l1);
            }
        }
    } else {
        // V: scatter-transpose to [bh][d][s]
        #pragma unroll
        for (int jn = 0; jn < 4; jn++) {
            const int ncol = n0 + wn + jn * 8 + ((lane & 3) << 1);
            const int hh = ncol >> 6;
            const int d  = ncol & 63;
            const float b0v = bias[ncol], b1v = bias[ncol + 1];
            #pragma unroll
            for (int im = 0; im < 2; im++) {
                const int row = m0 + wm + im * 16 + (lane >> 2);
                const int bb = row >> 10;
                const int s  = row & (S_ - 1);
                const int vb = ((bb * H_ + hh) * D_ + d) * S_ + s;
                __nv_bfloat16 h, l;
                split_bf16(acc[im][jn][0] + b0v, h, l);
                g_vth[vb] = h;            g_vtl[vb] = l;
                split_bf16(acc[im][jn][1] + b1v, h, l);
                g_vth[vb + S_] = h;       g_vtl[vb + S_] = l;
                split_bf16(acc[im][jn][2] + b0v, h, l);
                g_vth[vb + 8] = h;        g_vtl[vb + 8] = l;
                split_bf16(acc[im][jn][3] + b1v, h, l);
                g_vth[vb + S_ + 8] = h;   g_vtl[vb + S_ + 8] = l;
            }
        }
    }
}

// ---------------------------------------------------------------------------
// MMA flash attention (bf16 3-pass) with cp.async 2-stage K/V pipeline.
// 128 threads (4 warps), 64 q rows per block.  (R12 version, verbatim.)
// ---------------------------------------------------------------------------
#define ALD 72
#define ATILE (64 * ALD)
#define AT_SMEM_BYTES ((2 + 8) * ATILE * 2)

__device__ __forceinline__ void attn_issue(
    __nv_bfloat16* stage_base, int bh, size_t qoff, int t0, int tid)
{
    #pragma unroll
    for (int u = 0; u < 4; u++) {
        const int idx = tid + u * 128;
        const int r  = idx >> 3;
        const int sg = (idx & 7) * 8;
        const uint32_t doff = (uint32_t)(r * ALD + sg);
        cp_async16(smem_u32(stage_base + 0 * ATILE + doff),
                   g_kh + qoff + (t0 + r) * D_ + sg);
        cp_async16(smem_u32(stage_base + 1 * ATILE + doff),
                   g_kl + qoff + (t0 + r) * D_ + sg);
        cp_async16(smem_u32(stage_base + 2 * ATILE + doff),
                   g_vth + (size_t)(bh * D_ + r) * S_ + t0 + sg);
        cp_async16(smem_u32(stage_base + 3 * ATILE + doff),
                   g_vtl + (size_t)(bh * D_ + r) * S_ + t0 + sg);
    }
    cp_commit();
}

__global__ __launch_bounds__(128)
void attn_mma(const int* __restrict__ lens, float* __restrict__ out)
{
    extern __shared__ char smem_raw[];
    __nv_bfloat16* Qh = (__nv_bfloat16*)smem_raw;
    __nv_bfloat16* Ql = Qh + ATILE;
    __nv_bfloat16* St = Ql + ATILE;   // stage s at St + s*4*ATILE

    const int bh = blockIdx.y;
    const int b  = bh >> 4;
    const int h  = bh & (H_ - 1);
    const int len = lens[b];
    const int q0 = blockIdx.x * 64;
    const int tid = threadIdx.x;

    // ---- Shortcut: whole block invalid -> uniform mean of V ----
    if (q0 >= len) {
        float* red = (float*)smem_raw;
        const int d = tid & 63;
        const int half = tid >> 6;
        const uint4* ph = (const uint4*)(g_vth + (bh * D_ + d) * S_) + half * 64;
        const uint4* pl = (const uint4*)(g_vtl + (bh * D_ + d) * S_) + half * 64;
        float a = 0.f;
        for (int i = 0; i < 64; i++) {
            uint4 xh = ph[i], xl = pl[i];
            const __nv_bfloat162* eh = (const __nv_bfloat162*)&xh;
            const __nv_bfloat162* el = (const __nv_bfloat162*)&xl;
            #pragma unroll
            for (int e = 0; e < 4; e++) {
                float2 fh = __bfloat1622float2(eh[e]);
                float2 fl = __bfloat1622float2(el[e]);
                a += fh.x + fh.y + fl.x + fl.y;
            }
        }
        red[half * 64 + d] = a;
        __syncthreads();
        const float m = (red[d] + red[64 + d]) * (1.0f / 1024.0f);
        for (int r = half; r < 64; r += 2)
            out[(b * S_ + q0 + r) * E_ + h * D_ + d] = m;
        return;
    }

    const int warp = tid >> 5;
    const int lane = tid & 31;
    const int wm = warp * 16;

    const size_t qoff = (size_t)bh * S_ * D_;

    const bool all_valid = (q0 + 64 <= len);
    const int kend = all_valid ? ((len + 63) & ~63) : S_;
    const int nt = kend >> 6;

    // Start pipeline
    attn_issue(St, bh, qoff, 0, tid);
    if (nt > 1) attn_issue(St + 4 * ATILE, bh, qoff, 64, tid);

    // Load Q (overlaps with in-flight cp.async)
    #pragma unroll
    for (int u = 0; u < 4; u++) {
        const int idx = tid + u * 128;
        const int r = idx >> 3, seg = idx & 7;
        *(uint4*)&Qh[r * ALD + seg * 8] = *(const uint4*)&g_qh[qoff + (q0 + r) * D_ + seg * 8];
        *(uint4*)&Ql[r * ALD + seg * 8] = *(const uint4*)&g_ql[qoff + (q0 + r) * D_ + seg * 8];
    }

    float m0 = -CUDART_INF_F, m1 = -CUDART_INF_F, l0 = 0.f, l1 = 0.f;
    float o[8][4];
    #pragma unroll
    for (int j = 0; j < 8; j++)
        #pragma unroll
        for (int e = 0; e < 4; e++) o[j][e] = 0.f;

    const float scale = 0.125f;
    const int r0g = q0 + wm + (lane >> 2);
    const int r1g = r0g + 8;
    const bool rv0 = r0g < len, rv1 = r1g < len;

    for (int ti = 0; ti < nt; ti++) {
        const int st = ti & 1;
        const int t0 = ti * 64;
        if (ti + 1 < nt) cp_wait1(); else cp_wait0();
        __syncthreads();

        const __nv_bfloat16* Kh  = St + st * 4 * ATILE;
        const __nv_bfloat16* Kl  = Kh + ATILE;
        const __nv_bfloat16* Vth = Kh + 2 * ATILE;
        const __nv_bfloat16* Vtl = Kh + 3 * ATILE;

        // ---- S = Q K^T ----
        float sc[8][4];
        #pragma unroll
        for (int j = 0; j < 8; j++)
            #pragma unroll
            for (int e = 0; e < 4; e++) sc[j][e] = 0.f;

        #pragma unroll
        for (int kk = 0; kk < 64; kk += 16) {
            uint32_t ah[4], al[4];
            const int ar = wm + (lane >> 2);
            const int ac = kk + ((lane & 3) << 1);
            ah[0] = *(const uint32_t*)&Qh[ ar      * ALD + ac    ];
            ah[1] = *(const uint32_t*)&Qh[(ar + 8) * ALD + ac    ];
            ah[2] = *(const uint32_t*)&Qh[ ar      * ALD + ac + 8];
            ah[3] = *(const uint32_t*)&Qh[(ar + 8) * ALD + ac + 8];
            al[0] = *(const uint32_t*)&Ql[ ar      * ALD + ac    ];
            al[1] = *(const uint32_t*)&Ql[(ar + 8) * ALD + ac    ];
            al[2] = *(const uint32_t*)&Ql[ ar      * ALD + ac + 8];
            al[3] = *(const uint32_t*)&Ql[(ar + 8) * ALD + ac + 8];
            #pragma unroll
            for (int j = 0; j < 8; j++) {
                const int br = j * 8 + (lane >> 2);
                const int bc = kk + ((lane & 3) << 1);
                uint32_t bhf[2], blf[2];
                bhf[0] = *(const uint32_t*)&Kh[br * ALD + bc    ];
                bhf[1] = *(const uint32_t*)&Kh[br * ALD + bc + 8];
                blf[0] = *(const uint32_t*)&Kl[br * ALD + bc    ];
                blf[1] = *(const uint32_t*)&Kl[br * ALD + bc + 8];
                mma16816(sc[j], ah, bhf);
                mma16816(sc[j], ah, blf);
                mma16816(sc[j], al, bhf);
            }
        }

        // ---- mask + scale ----
        #pragma unroll
        for (int j = 0; j < 8; j++) {
            const int c0 = t0 + j * 8 + ((lane & 3) << 1);
            const bool cv0 = c0 < len, cv1 = (c0 + 1) < len;
            sc[j][0] = (rv0 && cv0) ? sc[j][0] * scale : -1e9f;
            sc[j][1] = (rv0 && cv1) ? sc[j][1] * scale : -1e9f;
            sc[j][2] = (rv1 && cv0) ? sc[j][2] * scale : -1e9f;
            sc[j][3] = (rv1 && cv1) ? sc[j][3] * scale : -1e9f;
        }

        // ---- online softmax ----
        float vm0 = -CUDART_INF_F, vm1 = -CUDART_INF_F;
        #pragma unroll
        for (int j = 0; j < 8; j++) {
            vm0 = fmaxf(vm0, fmaxf(sc[j][0], sc[j][1]));
            vm1 = fmaxf(vm1, fmaxf(sc[j][2], sc[j][3]));
        }
        vm0 = fmaxf(vm0, __shfl_xor_sync(0xffffffffu, vm0, 1));
        vm0 = fmaxf(vm0, __shfl_xor_sync(0xffffffffu, vm0, 2));
        vm1 = fmaxf(vm1, __shfl_xor_sync(0xffffffffu, vm1, 1));
        vm1 = fmaxf(vm1, __shfl_xor_sync(0xffffffffu, vm1, 2));
        const float mn0 = fmaxf(m0, vm0);
        const float mn1 = fmaxf(m1, vm1);
        const float al0 = __expf(m0 - mn0);
        const float al1 = __expf(m1 - mn1);
        m0 = mn0; m1 = mn1;

        float s0 = 0.f, s1 = 0.f;
        #pragma unroll
        for (int j = 0; j < 8; j++) {
            sc[j][0] = __expf(sc[j][0] - mn0); s0 += sc[j][0];
            sc[j][1] = __expf(sc[j][1] - mn0); s0 += sc[j][1];
            sc[j][2] = __expf(sc[j][2] - mn1); s1 += sc[j][2];
            sc[j][3] = __expf(sc[j][3] - mn1); s1 += sc[j][3];
        }
        s0 += __shfl_xor_sync(0xffffffffu, s0, 1);
        s0 += __shfl_xor_sync(0xffffffffu, s0, 2);
        s1 += __shfl_xor_sync(0xffffffffu, s1, 1);
        s1 += __shfl_xor_sync(0xffffffffu, s1, 2);
        l0 = l0 * al0 + s0;
        l1 = l1 * al1 + s1;
        #pragma unroll
        for (int j = 0; j < 8; j++) {
            o[j][0] *= al0; o[j][1] *= al0;
            o[j][2] *= al1; o[j][3] *= al1;
        }

        // ---- O += P V ----
        #pragma unroll
        for (int kp = 0; kp < 4; kp++) {
            const int j0 = kp * 2, j1 = kp * 2 + 1;
            uint32_t pah[4], pal[4];
            {
                __nv_bfloat16 hx, lx, hy, ly;
                split_bf16(sc[j0][0], hx, lx); split_bf16(sc[j0][1], hy, ly);
                pah[0] = pack_bf2(hx, hy); pal[0] = pack_bf2(lx, ly);
                split_bf16(sc[j0][2], hx, lx); split_bf16(sc[j0][3], hy, ly);
                pah[1] = pack_bf2(hx, hy); pal[1] = pack_bf2(lx, ly);
                split_bf16(sc[j1][0], hx, lx); split_bf16(sc[j1][1], hy, ly);
                pah[2] = pack_bf2(hx, hy); pal[2] = pack_bf2(lx, ly);
                split_bf16(sc[j1][2], hx, lx); split_bf16(sc[j1][3], hy, ly);
                pah[3] = pack_bf2(hx, hy); pal[3] = pack_bf2(lx, ly);
            }
            #pragma unroll
            for (int j = 0; j < 8; j++) {
                const int br = j * 8 + (lane >> 2);
                const int bc = kp * 16 + ((lane & 3) << 1);
                uint32_t bhf[2], blf[2];
                bhf[0] = *(const uint32_t*)&Vth[br * ALD + bc    ];
                bhf[1] = *(const uint32_t*)&Vth[br * ALD + bc + 8];
                blf[0] = *(const uint32_t*)&Vtl[br * ALD + bc    ];
                blf[1] = *(const uint32_t*)&Vtl[br * ALD + bc + 8];
                mma16816(o[j], pah, bhf);
                mma16816(o[j], pah, blf);
                mma16816(o[j], pal, bhf);
            }
        }

        __syncthreads();
        if (ti + 2 < nt)
            attn_issue(St + st * 4 * ATILE, bh, qoff, (ti + 2) * 64, tid);
    }

    const float inv0 = 1.f / l0;
    const float inv1 = 1.f / l1;
    #pragma unroll
    for (int j = 0; j < 8; j++) {
        const int d = j * 8 + ((lane & 3) << 1);
        float2 w0 = make_float2(o[j][0] * inv0, o[j][1] * inv0);
        float2 w1 = make_float2(o[j][2] * inv1, o[j][3] * inv1);
        *(float2*)&out[(b * S_ + r0g) * E_ + h * D_ + d] = w0;
        *(float2*)&out[(b * S_ + r1g) * E_ + h * D_ + d] = w1;
    }
}

// ---------------------------------------------------------------------------
extern "C" void kernel_launch(void* const* d_in, const int* in_sizes, int n_in,
                              void* d_out, int out_size)
{
    const float* x   = (const float*)d_in[0];
    const float* Wq  = (const float*)d_in[1];
    const float* bq  = (const float*)d_in[2];
    const float* Wk  = (const float*)d_in[3];
    const float* bk  = (const float*)d_in[4];
    const float* Wv  = (const float*)d_in[5];
    const float* bv  = (const float*)d_in[6];
    const int*  lens = (const int*)d_in[7];
    float* out = (float*)d_out;

    // Projections: TF32 single-pass, tile 128x64 (finer wave granularity)
    cudaFuncSetAttribute(qkv_mma,
                         cudaFuncAttributeMaxDynamicSharedMemorySize, QKV_SMEM);
    dim3 ggrid(E_ / TBN, M_ / TBM, 3);
    qkv_mma<<<ggrid, 256, QKV_SMEM>>>(x, Wq, bq, Wk, bk, Wv, bv);

    // Attention (R12 form, frozen)
    cudaFuncSetAttribute(attn_mma,
                         cudaFuncAttributeMaxDynamicSharedMemorySize, AT_SMEM_BYTES);
    dim3 agrid(S_ / 64, B_ * H_);
    attn_mma<<<agrid, 128, AT_SMEM_BYTES>>>(lens, out);
}

// round 16
// speedup vs baseline: 1.1072x; 1.0647x over previous
#include <cuda_runtime.h>
#include <cuda_bf16.h>
#include <math_constants.h>
#include <cstdint>

// Problem constants (fixed by the dataset)
#define B_  4
#define S_  1024
#define E_  1024
#define H_  16
#define D_  64
#define M_  (B_ * S_)

// Split-bf16 Q/K/V scratch. Q/K row-major [bh][s][d]; V transposed [bh][d][s].
__device__ __nv_bfloat16 g_qh[B_*H_*S_*D_], g_ql[B_*H_*S_*D_];
__device__ __nv_bfloat16 g_kh[B_*H_*S_*D_], g_kl[B_*H_*S_*D_];
__device__ __nv_bfloat16 g_vth[B_*H_*S_*D_], g_vtl[B_*H_*S_*D_];

// ---------------------------------------------------------------------------
// Helpers
// ---------------------------------------------------------------------------
__device__ __forceinline__ void mma16816(float* d, const uint32_t* a, const uint32_t* b) {
    asm volatile(
        "mma.sync.aligned.m16n8k16.row.col.f32.bf16.bf16.f32 "
        "{%0,%1,%2,%3}, {%4,%5,%6,%7}, {%8,%9}, {%0,%1,%2,%3};\n"
        : "+f"(d[0]), "+f"(d[1]), "+f"(d[2]), "+f"(d[3])
        : "r"(a[0]), "r"(a[1]), "r"(a[2]), "r"(a[3]), "r"(b[0]), "r"(b[1]));
}

__device__ __forceinline__ void mma1688_tf32(float* d, const uint32_t* a, const uint32_t* b) {
    asm volatile(
        "mma.sync.aligned.m16n8k8.row.col.f32.tf32.tf32.f32 "
        "{%0,%1,%2,%3}, {%4,%5,%6,%7}, {%8,%9}, {%0,%1,%2,%3};\n"
        : "+f"(d[0]), "+f"(d[1]), "+f"(d[2]), "+f"(d[3])
        : "r"(a[0]), "r"(a[1]), "r"(a[2]), "r"(a[3]), "r"(b[0]), "r"(b[1]));
}

__device__ __forceinline__ uint32_t to_tf32(float f) {
    uint32_t u;
    asm("cvt.rna.tf32.f32 %0, %1;" : "=r"(u) : "f"(f));
    return u;
}

__device__ __forceinline__ uint32_t pack_bf2(__nv_bfloat16 lo, __nv_bfloat16 hi) {
    uint32_t l = *(const unsigned short*)&lo;
    uint32_t h = *(const unsigned short*)&hi;
    return l | (h << 16);
}

__device__ __forceinline__ void split_bf16(float x, __nv_bfloat16& h, __nv_bfloat16& l) {
    h = __float2bfloat16(x);
    l = __float2bfloat16(x - __bfloat162float(h));
}

__device__ __forceinline__ uint32_t smem_u32(const void* p) {
    return (uint32_t)__cvta_generic_to_shared(p);
}

__device__ __forceinline__ void cp_async16(uint32_t dst, const void* src) {
    asm volatile("cp.async.cg.shared.global [%0], [%1], 16;\n" :: "r"(dst), "l"(src));
}

__device__ __forceinline__ void cp_commit() {
    asm volatile("cp.async.commit_group;" ::: "memory");
}

__device__ __forceinline__ void cp_wait2() {
    asm volatile("cp.async.wait_group 2;" ::: "memory");
}

__device__ __forceinline__ void cp_wait1() {
    asm volatile("cp.async.wait_group 1;" ::: "memory");
}

__device__ __forceinline__ void cp_wait0() {
    asm volatile("cp.async.wait_group 0;" ::: "memory");
}

// ---------------------------------------------------------------------------
// QKV projection GEMM: TF32 single-pass, tile 128x128 (R12 config), with a
// 3-stage cp.async pipeline (2 tiles in flight ahead of compute).
// 256 threads, warp tile 64x32. blockIdx.z = Q/K/V.
// ---------------------------------------------------------------------------
#define TBM 128
#define TBN 128
#define TBK 32
#define LDA_W 36                 // A row stride in words (32 + 4)
#define LDB_W 136                // B row stride in words (128 + 8)
#define ATW (TBM * LDA_W)
#define BTW (TBK * LDB_W)
#define NSTAGE 3
#define QKV_SMEM (NSTAGE * (ATW + BTW) * 4)

__device__ __forceinline__ void qkv_issue(
    float* sm, int st,
    const float* __restrict__ X, const float* __restrict__ W,
    int m0, int n0, int k0, int tid)
{
    float* Abase = sm + st * (ATW + BTW);
    float* Bbase = Abase + ATW;
    #pragma unroll
    for (int u = 0; u < 4; u++) {
        const int idx = tid + u * 256;
        const int row = idx >> 3, seg = idx & 7;               // A: 128 rows x 8 f4
        cp_async16(smem_u32(Abase + row * LDA_W + seg * 4),
                   X + (m0 + row) * E_ + k0 + seg * 4);
    }
    #pragma unroll
    for (int u = 0; u < 4; u++) {
        const int idx = tid + u * 256;
        const int kr = idx >> 5, nq = idx & 31;                // B: 32 k x 32 f4
        cp_async16(smem_u32(Bbase + kr * LDB_W + nq * 4),
                   W + (k0 + kr) * E_ + n0 + nq * 4);
    }
    cp_commit();
}

__global__ __launch_bounds__(256)
void qkv_mma(const float* __restrict__ X,
             const float* __restrict__ Wq, const float* __restrict__ bq,
             const float* __restrict__ Wk, const float* __restrict__ bk,
             const float* __restrict__ Wv, const float* __restrict__ bv)
{
    extern __shared__ float qsm[];

    const int which = blockIdx.z;
    const float* __restrict__ W    = (which == 0) ? Wq : (which == 1) ? Wk : Wv;
    const float* __restrict__ bias = (which == 0) ? bq : (which == 1) ? bk : bv;

    const int m0 = blockIdx.y * TBM;
    const int n0 = blockIdx.x * TBN;
    const int tid  = threadIdx.x;
    const int warp = tid >> 5;
    const int lane = tid & 31;
    const int wm = (warp >> 2) * 64;
    const int wn = (warp & 3) * 32;

    float acc[4][4][4];
    #pragma unroll
    for (int i = 0; i < 4; i++)
        #pragma unroll
        for (int j = 0; j < 4; j++)
            #pragma unroll
            for (int r = 0; r < 4; r++) acc[i][j][r] = 0.f;

    qkv_issue(qsm, 0, X, W, m0, n0, 0, tid);
    qkv_issue(qsm, 1, X, W, m0, n0, TBK, tid);
    qkv_issue(qsm, 2, X, W, m0, n0, 2 * TBK, tid);

    int st = 0;
    for (int i = 0; i < 32; i++) {
        if (i < 30) cp_wait2();
        else if (i == 30) cp_wait1();
        else cp_wait0();
        __syncthreads();

        const float* As = qsm + st * (ATW + BTW);
        const float* Bs = As + ATW;

        #pragma unroll
        for (int ks = 0; ks < TBK; ks += 8) {
            uint32_t a[4][4];
            const int arow = wm + (lane >> 2);
            const int acol = ks + (lane & 3);
            #pragma unroll
            for (int im = 0; im < 4; im++) {
                const int r = arow + im * 16;
                a[im][0] = to_tf32(As[ r      * LDA_W + acol    ]);
                a[im][1] = to_tf32(As[(r + 8) * LDA_W + acol    ]);
                a[im][2] = to_tf32(As[ r      * LDA_W + acol + 4]);
                a[im][3] = to_tf32(As[(r + 8) * LDA_W + acol + 4]);
            }
            uint32_t bfr[4][2];
            const int bk0 = ks + (lane & 3);
            const int bn  = wn + (lane >> 2);
            #pragma unroll
            for (int jn = 0; jn < 4; jn++) {
                const int n = bn + jn * 8;
                bfr[jn][0] = to_tf32(Bs[ bk0      * LDB_W + n]);
                bfr[jn][1] = to_tf32(Bs[(bk0 + 4) * LDB_W + n]);
            }
            #pragma unroll
            for (int im = 0; im < 4; im++)
                #pragma unroll
                for (int jn = 0; jn < 4; jn++)
                    mma1688_tf32(acc[im][jn], a[im], bfr[jn]);
        }
        __syncthreads();
        if (i + NSTAGE < 32)
            qkv_issue(qsm, st, X, W, m0, n0, (i + NSTAGE) * TBK, tid);
        st = (st == NSTAGE - 1) ? 0 : st + 1;
    }

    // ---- epilogue: add bias, split to bf16 hi/lo, write scratch ----
    if (which < 2) {
        __nv_bfloat16* __restrict__ oh = (which == 0) ? g_qh : g_kh;
        __nv_bfloat16* __restrict__ ol = (which == 0) ? g_ql : g_kl;
        #pragma unroll
        for (int jn = 0; jn < 4; jn++) {
            const int ncol = n0 + wn + jn * 8 + ((lane & 3) << 1);
            const int hh = ncol >> 6;
            const int d  = ncol & 63;
            const float b0v = bias[ncol], b1v = bias[ncol + 1];
            #pragma unroll
            for (int im = 0; im < 4; im++) {
                const int row = m0 + wm + im * 16 + (lane >> 2);
                const int bb = row >> 10;
                const int s  = row & (S_ - 1);
                const int base = ((bb * H_ + hh) * S_ + s) * D_ + d;
                __nv_bfloat16 h0, l0, h1, l1;
                split_bf16(acc[im][jn][0] + b0v, h0, l0);
                split_bf16(acc[im][jn][1] + b1v, h1, l1);
                *(uint32_t*)&oh[base] = pack_bf2(h0, h1);
                *(uint32_t*)&ol[base] = pack_bf2(l0, l1);
                split_bf16(acc[im][jn][2] + b0v, h0, l0);
                split_bf16(acc[im][jn][3] + b1v, h1, l1);
                *(uint32_t*)&oh[base + 8 * D_] = pack_bf2(h0, h1);
                *(uint32_t*)&ol[base + 8 * D_] = pack_bf2(l0, l1);
            }
        }
    } else {
        // V: scatter-transpose to [bh][d][s]
        #pragma unroll
        for (int jn = 0; jn < 4; jn++) {
            const int ncol = n0 + wn + jn * 8 + ((lane & 3) << 1);
            const int hh = ncol >> 6;
            const int d  = ncol & 63;
            const float b0v = bias[ncol], b1v = bias[ncol + 1];
            #pragma unroll
            for (int im = 0; im < 4; im++) {
                const int row = m0 + wm + im * 16 + (lane >> 2);
                const int bb = row >> 10;
                const int s  = row & (S_ - 1);
                const int vb = ((bb * H_ + hh) * D_ + d) * S_ + s;
                __nv_bfloat16 h, l;
                split_bf16(acc[im][jn][0] + b0v, h, l);
                g_vth[vb] = h;            g_vtl[vb] = l;
                split_bf16(acc[im][jn][1] + b1v, h, l);
                g_vth[vb + S_] = h;       g_vtl[vb + S_] = l;
                split_bf16(acc[im][jn][2] + b0v, h, l);
                g_vth[vb + 8] = h;        g_vtl[vb + 8] = l;
                split_bf16(acc[im][jn][3] + b1v, h, l);
                g_vth[vb + S_ + 8] = h;   g_vtl[vb + S_ + 8] = l;
            }
        }
    }
}

// ---------------------------------------------------------------------------
// MMA flash attention (bf16 3-pass) with cp.async 2-stage K/V pipeline.
// 128 threads (4 warps), 64 q rows per block.  (R12 version, verbatim.)
// ---------------------------------------------------------------------------
#define ALD 72
#define ATILE (64 * ALD)
#define AT_SMEM_BYTES ((2 + 8) * ATILE * 2)

__device__ __forceinline__ void attn_issue(
    __nv_bfloat16* stage_base, int bh, size_t qoff, int t0, int tid)
{
    #pragma unroll
    for (int u = 0; u < 4; u++) {
        const int idx = tid + u * 128;
        const int r  = idx >> 3;
        const int sg = (idx & 7) * 8;
        const uint32_t doff = (uint32_t)(r * ALD + sg);
        cp_async16(smem_u32(stage_base + 0 * ATILE + doff),
                   g_kh + qoff + (t0 + r) * D_ + sg);
        cp_async16(smem_u32(stage_base + 1 * ATILE + doff),
                   g_kl + qoff + (t0 + r) * D_ + sg);
        cp_async16(smem_u32(stage_base + 2 * ATILE + doff),
                   g_vth + (size_t)(bh * D_ + r) * S_ + t0 + sg);
        cp_async16(smem_u32(stage_base + 3 * ATILE + doff),
                   g_vtl + (size_t)(bh * D_ + r) * S_ + t0 + sg);
    }
    cp_commit();
}

__global__ __launch_bounds__(128)
void attn_mma(const int* __restrict__ lens, float* __restrict__ out)
{
    extern __shared__ char smem_raw[];
    __nv_bfloat16* Qh = (__nv_bfloat16*)smem_raw;
    __nv_bfloat16* Ql = Qh + ATILE;
    __nv_bfloat16* St = Ql + ATILE;   // stage s at St + s*4*ATILE

    const int bh = blockIdx.y;
    const int b  = bh >> 4;
    const int h  = bh & (H_ - 1);
    const int len = lens[b];
    const int q0 = blockIdx.x * 64;
    const int tid = threadIdx.x;

    // ---- Shortcut: whole block invalid -> uniform mean of V ----
    if (q0 >= len) {
        float* red = (float*)smem_raw;
        const int d = tid & 63;
        const int half = tid >> 6;
        const uint4* ph = (const uint4*)(g_vth + (bh * D_ + d) * S_) + half * 64;
        const uint4* pl = (const uint4*)(g_vtl + (bh * D_ + d) * S_) + half * 64;
        float a = 0.f;
        for (int i = 0; i < 64; i++) {
            uint4 xh = ph[i], xl = pl[i];
            const __nv_bfloat162* eh = (const __nv_bfloat162*)&xh;
            const __nv_bfloat162* el = (const __nv_bfloat162*)&xl;
            #pragma unroll
            for (int e = 0; e < 4; e++) {
                float2 fh = __bfloat1622float2(eh[e]);
                float2 fl = __bfloat1622float2(el[e]);
                a += fh.x + fh.y + fl.x + fl.y;
            }
        }
        red[half * 64 + d] = a;
        __syncthreads();
        const float m = (red[d] + red[64 + d]) * (1.0f / 1024.0f);
        for (int r = half; r < 64; r += 2)
            out[(b * S_ + q0 + r) * E_ + h * D_ + d] = m;
        return;
    }

    const int warp = tid >> 5;
    const int lane = tid & 31;
    const int wm = warp * 16;

    const size_t qoff = (size_t)bh * S_ * D_;

    const bool all_valid = (q0 + 64 <= len);
    const int kend = all_valid ? ((len + 63) & ~63) : S_;
    const int nt = kend >> 6;

    // Start pipeline
    attn_issue(St, bh, qoff, 0, tid);
    if (nt > 1) attn_issue(St + 4 * ATILE, bh, qoff, 64, tid);

    // Load Q (overlaps with in-flight cp.async)
    #pragma unroll
    for (int u = 0; u < 4; u++) {
        const int idx = tid + u * 128;
        const int r = idx >> 3, seg = idx & 7;
        *(uint4*)&Qh[r * ALD + seg * 8] = *(const uint4*)&g_qh[qoff + (q0 + r) * D_ + seg * 8];
        *(uint4*)&Ql[r * ALD + seg * 8] = *(const uint4*)&g_ql[qoff + (q0 + r) * D_ + seg * 8];
    }

    float m0 = -CUDART_INF_F, m1 = -CUDART_INF_F, l0 = 0.f, l1 = 0.f;
    float o[8][4];
    #pragma unroll
    for (int j = 0; j < 8; j++)
        #pragma unroll
        for (int e = 0; e < 4; e++) o[j][e] = 0.f;

    const float scale = 0.125f;
    const int r0g = q0 + wm + (lane >> 2);
    const int r1g = r0g + 8;
    const bool rv0 = r0g < len, rv1 = r1g < len;

    for (int ti = 0; ti < nt; ti++) {
        const int st = ti & 1;
        const int t0 = ti * 64;
        if (ti + 1 < nt) cp_wait1(); else cp_wait0();
        __syncthreads();

        const __nv_bfloat16* Kh  = St + st * 4 * ATILE;
        const __nv_bfloat16* Kl  = Kh + ATILE;
        const __nv_bfloat16* Vth = Kh + 2 * ATILE;
        const __nv_bfloat16* Vtl = Kh + 3 * ATILE;

        // ---- S = Q K^T ----
        float sc[8][4];
        #pragma unroll
        for (int j = 0; j < 8; j++)
            #pragma unroll
            for (int e = 0; e < 4; e++) sc[j][e] = 0.f;

        #pragma unroll
        for (int kk = 0; kk < 64; kk += 16) {
            uint32_t ah[4], al[4];
            const int ar = wm + (lane >> 2);
            const int ac = kk + ((lane & 3) << 1);
            ah[0] = *(const uint32_t*)&Qh[ ar      * ALD + ac    ];
            ah[1] = *(const uint32_t*)&Qh[(ar + 8) * ALD + ac    ];
            ah[2] = *(const uint32_t*)&Qh[ ar      * ALD + ac + 8];
            ah[3] = *(const uint32_t*)&Qh[(ar + 8) * ALD + ac + 8];
            al[0] = *(const uint32_t*)&Ql[ ar      * ALD + ac    ];
            al[1] = *(const uint32_t*)&Ql[(ar + 8) * ALD + ac    ];
            al[2] = *(const uint32_t*)&Ql[ ar      * ALD + ac + 8];
            al[3] = *(const uint32_t*)&Ql[(ar + 8) * ALD + ac + 8];
            #pragma unroll
            for (int j = 0; j < 8; j++) {
                const int br = j * 8 + (lane >> 2);
                const int bc = kk + ((lane & 3) << 1);
                uint32_t bhf[2], blf[2];
                bhf[0] = *(const uint32_t*)&Kh[br * ALD + bc    ];
                bhf[1] = *(const uint32_t*)&Kh[br * ALD + bc + 8];
                blf[0] = *(const uint32_t*)&Kl[br * ALD + bc    ];
                blf[1] = *(const uint32_t*)&Kl[br * ALD + bc + 8];
                mma16816(sc[j], ah, bhf);
                mma16816(sc[j], ah, blf);
                mma16816(sc[j], al, bhf);
            }
        }

        // ---- mask + scale ----
        #pragma unroll
        for (int j = 0; j < 8; j++) {
            const int c0 = t0 + j * 8 + ((lane & 3) << 1);
            const bool cv0 = c0 < len, cv1 = (c0 + 1) < len;
            sc[j][0] = (rv0 && cv0) ? sc[j][0] * scale : -1e9f;
            sc[j][1] = (rv0 && cv1) ? sc[j][1] * scale : -1e9f;
            sc[j][2] = (rv1 && cv0) ? sc[j][2] * scale : -1e9f;
            sc[j][3] = (rv1 && cv1) ? sc[j][3] * scale : -1e9f;
        }

        // ---- online softmax ----
        float vm0 = -CUDART_INF_F, vm1 = -CUDART_INF_F;
        #pragma unroll
        for (int j = 0; j < 8; j++) {
            vm0 = fmaxf(vm0, fmaxf(sc[j][0], sc[j][1]));
            vm1 = fmaxf(vm1, fmaxf(sc[j][2], sc[j][3]));
        }
        vm0 = fmaxf(vm0, __shfl_xor_sync(0xffffffffu, vm0, 1));
        vm0 = fmaxf(vm0, __shfl_xor_sync(0xffffffffu, vm0, 2));
        vm1 = fmaxf(vm1, __shfl_xor_sync(0xffffffffu, vm1, 1));
        vm1 = fmaxf(vm1, __shfl_xor_sync(0xffffffffu, vm1, 2));
        const float mn0 = fmaxf(m0, vm0);
        const float mn1 = fmaxf(m1, vm1);
        const float al0 = __expf(m0 - mn0);
        const float al1 = __expf(m1 - mn1);
        m0 = mn0; m1 = mn1;

        float s0 = 0.f, s1 = 0.f;
        #pragma unroll
        for (int j = 0; j < 8; j++) {
            sc[j][0] = __expf(sc[j][0] - mn0); s0 += sc[j][0];
            sc[j][1] = __expf(sc[j][1] - mn0); s0 += sc[j][1];
            sc[j][2] = __expf(sc[j][2] - mn1); s1 += sc[j][2];
            sc[j][3] = __expf(sc[j][3] - mn1); s1 += sc[j][3];
        }
        s0 += __shfl_xor_sync(0xffffffffu, s0, 1);
        s0 += __shfl_xor_sync(0xffffffffu, s0, 2);
        s1 += __shfl_xor_sync(0xffffffffu, s1, 1);
        s1 += __shfl_xor_sync(0xffffffffu, s1, 2);
        l0 = l0 * al0 + s0;
        l1 = l1 * al1 + s1;
        #pragma unroll
        for (int j = 0; j < 8; j++) {
            o[j][0] *= al0; o[j][1] *= al0;
            o[j][2] *= al1; o[j][3] *= al1;
        }

        // ---- O += P V ----
        #pragma unroll
        for (int kp = 0; kp < 4; kp++) {
            const int j0 = kp * 2, j1 = kp * 2 + 1;
            uint32_t pah[4], pal[4];
            {
                __nv_bfloat16 hx, lx, hy, ly;
                split_bf16(sc[j0][0], hx, lx); split_bf16(sc[j0][1], hy, ly);
                pah[0] = pack_bf2(hx, hy); pal[0] = pack_bf2(lx, ly);
                split_bf16(sc[j0][2], hx, lx); split_bf16(sc[j0][3], hy, ly);
                pah[1] = pack_bf2(hx, hy); pal[1] = pack_bf2(lx, ly);
                split_bf16(sc[j1][0], hx, lx); split_bf16(sc[j1][1], hy, ly);
                pah[2] = pack_bf2(hx, hy); pal[2] = pack_bf2(lx, ly);
                split_bf16(sc[j1][2], hx, lx); split_bf16(sc[j1][3], hy, ly);
                pah[3] = pack_bf2(hx, hy); pal[3] = pack_bf2(lx, ly);
            }
            #pragma unroll
            for (int j = 0; j < 8; j++) {
                const int br = j * 8 + (lane >> 2);
                const int bc = kp * 16 + ((lane & 3) << 1);
                uint32_t bhf[2], blf[2];
                bhf[0] = *(const uint32_t*)&Vth[br * ALD + bc    ];
                bhf[1] = *(const uint32_t*)&Vth[br * ALD + bc + 8];
                blf[0] = *(const uint32_t*)&Vtl[br * ALD + bc    ];
                blf[1] = *(const uint32_t*)&Vtl[br * ALD + bc + 8];
                mma16816(o[j], pah, bhf);
                mma16816(o[j], pah, blf);
                mma16816(o[j], pal, bhf);
            }
        }

        __syncthreads();
        if (ti + 2 < nt)
            attn_issue(St + st * 4 * ATILE, bh, qoff, (ti + 2) * 64, tid);
    }

    const float inv0 = 1.f / l0;
    const float inv1 = 1.f / l1;
    #pragma unroll
    for (int j = 0; j < 8; j++) {
        const int d = j * 8 + ((lane & 3) << 1);
        float2 w0 = make_float2(o[j][0] * inv0, o[j][1] * inv0);
        float2 w1 = make_float2(o[j][2] * inv1, o[j][3] * inv1);
        *(float2*)&out[(b * S_ + r0g) * E_ + h * D_ + d] = w0;
        *(float2*)&out[(b * S_ + r1g) * E_ + h * D_ + d] = w1;
    }
}

// ---------------------------------------------------------------------------
extern "C" void kernel_launch(void* const* d_in, const int* in_sizes, int n_in,
                              void* d_out, int out_size)
{
    const float* x   = (const float*)d_in[0];
    const float* Wq  = (const float*)d_in[1];
    const float* bq  = (const float*)d_in[2];
    const float* Wk  = (const float*)d_in[3];
    const float* bk  = (const float*)d_in[4];
    const float* Wv  = (const float*)d_in[5];
    const float* bv  = (const float*)d_in[6];
    const int*  lens = (const int*)d_in[7];
    float* out = (float*)d_out;

    // Projections: TF32 single-pass 128x128, 3-stage cp.async pipeline
    cudaFuncSetAttribute(qkv_mma,
                         cudaFuncAttributeMaxDynamicSharedMemorySize, QKV_SMEM);
    dim3 ggrid(E_ / TBN, M_ / TBM, 3);
    qkv_mma<<<ggrid, 256, QKV_SMEM>>>(x, Wq, bq, Wk, bk, Wv, bv);

    // Attention (R12 form, frozen)
    cudaFuncSetAttribute(attn_mma,
                         cudaFuncAttributeMaxDynamicSharedMemorySize, AT_SMEM_BYTES);
    dim3 agrid(S_ / 64, B_ * H_);
    attn_mma<<<agrid, 128, AT_SMEM_BYTES>>>(lens, out);
}